// round 16
// baseline (speedup 1.0000x reference)
#include <cuda_runtime.h>
#include <cuda_bf16.h>
#include <math.h>
#include <stdint.h>

#define BS    32
#define SEQ   2048
#define ENC   512
#define HEADS 8
#define IH    1024
#define DECIN 1024
#define SENT  0xFFFFFFFFu

#define MT 128           // rows per m-tile (k2a)
#define NT 64
#define NJT (IH / NT)
#define KC 64
#define MAXTILES 512

// ---------------- scratch ----------------
__device__ float         g_qv[BS][IH];
__device__ float         g_beta[BS][HEADS];
__device__ float         g_kap[BS][HEADS];
__device__ int           g_lo[BS];
__device__ int           g_hi[BS];
__device__ unsigned      g_rows[BS * SEQ + 128];
__device__ float         g_pf[BS][SEQ][NJT * HEADS];
__device__ float         g_ctx[BS][HEADS * ENC];
__device__ __nv_bfloat16 g_WvThi[IH * ENC];
__device__ __nv_bfloat16 g_WvTlo[IH * ENC];
__device__ __nv_bfloat16 g_Ahi[(size_t)MAXTILES * 128 * ENC];
__device__ __nv_bfloat16 g_Alo[(size_t)MAXTILES * 128 * ENC];

__device__ __forceinline__ float softplusf(float x) {
    return fmaxf(x, 0.f) + log1pf(expf(-fabsf(x)));
}

#define SW128(x) ((x) ^ (((x) >> 3) & 0x70))

__device__ __forceinline__ uint32_t smem_u32(const void* p) {
    uint32_t a;
    asm("{ .reg .u64 t; cvta.to.shared.u64 t, %1; cvt.u32.u64 %0, t; }" : "=r"(a) : "l"(p));
    return a;
}
__device__ __forceinline__ void ldsm4(uint32_t* r, uint32_t addr) {
    asm volatile("ldmatrix.sync.aligned.m8n8.x4.shared.b16 {%0,%1,%2,%3}, [%4];"
                 : "=r"(r[0]), "=r"(r[1]), "=r"(r[2]), "=r"(r[3]) : "r"(addr));
}
__device__ __forceinline__ void mma16816(float* c, const uint32_t* a,
                                         uint32_t b0, uint32_t b1) {
    asm volatile("mma.sync.aligned.m16n8k16.row.col.f32.bf16.bf16.f32 "
                 "{%0,%1,%2,%3}, {%4,%5,%6,%7}, {%8,%9}, {%0,%1,%2,%3};"
                 : "+f"(c[0]), "+f"(c[1]), "+f"(c[2]), "+f"(c[3])
                 : "r"(a[0]), "r"(a[1]), "r"(a[2]), "r"(a[3]), "r"(b0), "r"(b1));
}
__device__ __forceinline__ void cp16(uint32_t dst, const void* src) {
    asm volatile("cp.async.cg.shared.global [%0], [%1], 16;" :: "r"(dst), "l"(src));
}
#define CP_COMMIT() asm volatile("cp.async.commit_group;" ::: "memory")
#define CP_WAIT(n)  asm volatile("cp.async.wait_group %0;" :: "n"(n) : "memory")

__global__ void k_nop() {}

// ---------------- k_prep: kW (0..511) + k1 (512..767) + k0 (768..799) ----------------
__global__ void __launch_bounds__(256) k_prep(const float* __restrict__ Wv,
                                              const float* __restrict__ dec,
                                              const float* __restrict__ Wq,
                                              const float* __restrict__ bq,
                                              const float* __restrict__ bv,
                                              const float* __restrict__ kappa_in,
                                              const float* __restrict__ Wb,
                                              const float* __restrict__ bb,
                                              const float* __restrict__ Wk,
                                              const float* __restrict__ bk,
                                              float* __restrict__ out_kappa) {
    __shared__ float smem[4 * DECIN + 1024];
    int bid = blockIdx.x;
    int tid = threadIdx.x;

    if (bid < 512) {
        float (*s)[33] = (float (*)[33])smem;
        int k0 = (bid & 15) * 32, j0 = (bid >> 4) * 32;
        int jl = tid & 31, kq = tid >> 5;
        #pragma unroll
        for (int i = 0; i < 4; i++)
            s[kq * 4 + i][jl] = Wv[(size_t)(k0 + kq * 4 + i) * IH + j0 + jl];
        __syncthreads();
        int jr = tid >> 3;
        int kg = (tid & 7) * 4;
        __nv_bfloat16 hi[4], lo[4];
        #pragma unroll
        for (int i = 0; i < 4; i++) {
            float x = s[kg + i][jr];
            hi[i] = __float2bfloat16(x);
            lo[i] = __float2bfloat16(x - __bfloat162float(hi[i]));
        }
        size_t dst = (size_t)(j0 + jr) * ENC + k0 + kg;
        *(uint2*)(g_WvThi + dst) = *(const uint2*)hi;
        *(uint2*)(g_WvTlo + dst) = *(const uint2*)lo;
    } else if (bid < 768) {
        int id = bid - 512;
        int jt = id & 31, bg = id >> 5;
        int c  = tid & 31;
        int ks = tid >> 5;
        int j  = jt * 32 + c;
        float (*sdec)[DECIN] = (float (*)[DECIN])smem;
        float (*pacc)[4][32] = (float (*)[4][32])(smem + 4 * DECIN);
        for (int i = tid; i < 4 * DECIN; i += 256) {
            int bb2 = i >> 10, k = i & (DECIN - 1);
            sdec[bb2][k] = dec[(bg * 4 + bb2) * DECIN + k];
        }
        __syncthreads();
        float a0 = 0.f, a1 = 0.f, a2 = 0.f, a3 = 0.f;
        int k0 = ks * 128;
        #pragma unroll 16
        for (int k = k0; k < k0 + 128; k++) {
            float w = Wq[(size_t)k * IH + j];
            a0 += sdec[0][k] * w; a1 += sdec[1][k] * w;
            a2 += sdec[2][k] * w; a3 += sdec[3][k] * w;
        }
        pacc[ks][0][c] = a0; pacc[ks][1][c] = a1;
        pacc[ks][2][c] = a2; pacc[ks][3][c] = a3;
        __syncthreads();
        if (tid < 128) {
            int bb2 = tid >> 5;
            float s2 = 0.f;
            #pragma unroll
            for (int kk = 0; kk < 8; kk++) s2 += pacc[kk][bb2][c];
            g_qv[bg * 4 + bb2][j] = s2 + bq[j] + bv[j];
        }
    } else {
        int b = bid - 768;
        float* sdec = smem;
        float* sred = smem + DECIN;
        float* sbeta = sred + 64;
        float* skap  = sbeta + HEADS;
        for (int i = tid; i < DECIN; i += 256)
            sdec[i] = dec[b * DECIN + i];
        __syncthreads();
        int w = tid >> 5, lane = tid & 31;
        int mat = w >> 2, q = w & 3;
        const float* W = (mat == 0) ? Wb : Wk;
        int base = q * 2048;
        float acc = 0.f;
        #pragma unroll 16
        for (int it = 0; it < 64; it++) {
            int e = base + it * 32 + lane;
            acc += sdec[e >> 3] * W[e];
        }
        acc += __shfl_xor_sync(0xffffffffu, acc, 8);
        acc += __shfl_xor_sync(0xffffffffu, acc, 16);
        if (lane < 8) sred[(mat * 4 + q) * 8 + lane] = acc;
        __syncthreads();
        if (tid < 16) {
            int h = tid & 7, mt2 = tid >> 3;
            float dot = sred[(mt2 * 4 + 0) * 8 + h] + sred[(mt2 * 4 + 1) * 8 + h]
                      + sred[(mt2 * 4 + 2) * 8 + h] + sred[(mt2 * 4 + 3) * 8 + h];
            if (mt2 == 0) {
                float bv2 = softplusf(dot + bb[h]);
                sbeta[h] = bv2;
                g_beta[b][h] = bv2;
            } else {
                float kv = kappa_in[b * HEADS + h] + softplusf(dot + bk[h]);
                skap[h] = kv;
                g_kap[b][h] = kv;
                out_kappa[b * HEADS + h] = kv;
            }
        }
        __syncthreads();
        if (tid == 0) {
            float lof = 1e30f, hif = -1e30f;
            for (int h = 0; h < HEADS; h++) {
                float R = sqrtf(110.f / sbeta[h]);
                lof = fminf(lof, skap[h] - R);
                hif = fmaxf(hif, skap[h] + R);
            }
            int lo, hi;
            if (hif < 0.f || lof > (float)(SEQ - 1)) { lo = 0; hi = -1; }
            else {
                lo = (int)floorf(lof); if (lo < 0) lo = 0;
                hi = (int)ceilf(hif);  if (hi > SEQ - 1) hi = SEQ - 1;
            }
            g_lo[b] = lo; g_hi[b] = hi;
        }
    }
}

// ---------------- kE: grid-stride tiles; grid (64, 9) ----------------
__global__ void __launch_bounds__(256) kE_split(const float* __restrict__ enc,
                                                float* __restrict__ out_score) {
    int tid = threadIdx.x;
    if (blockIdx.y == 8) {
        uint4 z = make_uint4(0, 0, 0, 0);
        #pragma unroll
        for (int i = 0; i < 8; i++)
            ((uint4*)out_score)[(blockIdx.x * 8 + i) * 256 + tid] = z;
        return;
    }
    __shared__ int soff[BS + 1];
    if (tid < 32) {
        int w = g_hi[tid] - g_lo[tid] + 1;
        if (w < 0) w = 0;
        int x = w;
        #pragma unroll
        for (int off = 1; off < 32; off <<= 1) {
            int y = __shfl_up_sync(0xffffffffu, x, off);
            if (tid >= off) x += y;
        }
        soff[tid + 1] = x;
        if (tid == 0) soff[0] = 0;
    }
    __syncthreads();
    int total = soff[BS];
    int snt = (total + 127) / 128;
    if (snt < 1) snt = 1;

    int row  = tid >> 1;
    int half = tid & 1;
    int colb = blockIdx.y * 64 + half * 32;

    for (int tile = blockIdx.x; tile < snt; tile += 64) {
        int grow = tile * 128 + row;
        unsigned m = SENT;
        if (grow < total) {
            int b = 0;
            #pragma unroll 8
            while (b < BS - 1 && grow >= soff[b + 1]) b++;
            m = ((unsigned)b << 16) | (unsigned)(g_lo[b] + (grow - soff[b]));
        }
        if (blockIdx.y == 0 && half == 0)
            g_rows[grow] = m;

        size_t dbase = (size_t)grow * ENC + colb;
        if (m == SENT) {
            uint4 z = make_uint4(0, 0, 0, 0);
            #pragma unroll
            for (int q = 0; q < 4; q++) {
                ((uint4*)(g_Ahi + dbase))[q] = z;
                ((uint4*)(g_Alo + dbase))[q] = z;
            }
            continue;
        }
        const float4* src = (const float4*)(enc + ((size_t)(m >> 16) * SEQ + (m & 0xFFFF)) * ENC + colb);
        #pragma unroll
        for (int q = 0; q < 4; q++) {
            float4 v0 = src[q * 2], v1 = src[q * 2 + 1];
            float x[8] = {v0.x, v0.y, v0.z, v0.w, v1.x, v1.y, v1.z, v1.w};
            __nv_bfloat16 hi[8], lo[8];
            #pragma unroll
            for (int i = 0; i < 8; i++) {
                hi[i] = __float2bfloat16(x[i]);
                lo[i] = __float2bfloat16(x[i] - __bfloat162float(hi[i]));
            }
            ((uint4*)(g_Ahi + dbase))[q] = *(const uint4*)hi;
            ((uint4*)(g_Alo + dbase))[q] = *(const uint4*)lo;
        }
    }
}

// ---------------- K2a: 128x64 tiles, 8 warps (16 rows x 64 j each), cp.async pipeline ----------------
#define ST_STRIDE 49152
#define OFF_AH 0
#define OFF_AL 16384
#define OFF_BH 32768
#define OFF_BL 40960
#define OFF_WF   (2 * ST_STRIDE)
#define OFF_META (OFF_WF + 2048)
#define SMEM_DYN (OFF_META + 512 + 1024)

__global__ void __launch_bounds__(256) k2a_mma(const float* __restrict__ Wf) {
    extern __shared__ char dsm[];
    uint32_t b0 = smem_u32(dsm);
    uint32_t ab = (b0 + 1023u) & ~1023u;
    char* dyn = dsm + (ab - b0);
    float*    sWf   = (float*)(dyn + OFF_WF);
    unsigned* smeta = (unsigned*)(dyn + OFF_META);
    __shared__ int s_tt;

    int tid  = threadIdx.x;
    int wid  = tid >> 5, lane = tid & 31;

    if (tid == 0) {
        int off = 0;
        for (int b = 0; b < BS; b++) {
            int w = g_hi[b] - g_lo[b] + 1;
            if (w > 0) off += w;
        }
        int n128 = (off + MT - 1) / MT;
        if (n128 < 1) n128 = 1;
        s_tt = n128 * NJT;
    }
    __syncthreads();
    int total_tiles = s_tt;

    int wm = wid * 16;
    uint32_t a_rb  = (uint32_t)((wm + (lane & 15)) * 128 + ((lane & 16) ? 16 : 0));
    uint32_t a_msk = (a_rb >> 3) & 0x70;
    uint32_t b_rb[4], b_msk[4];
    #pragma unroll
    for (int p = 0; p < 4; p++) {
        int n = p * 16 + (lane & 7) + ((lane & 16) ? 8 : 0);
        b_rb[p]  = (uint32_t)(n * 128 + ((lane & 8) ? 16 : 0));
        b_msk[p] = (b_rb[p] >> 3) & 0x70;
    }

    int arow = tid >> 1, ahalf = tid & 1;     // A: 128 rows x 2 halves, 4 cp16 each
    int brow = tid >> 2, bq2 = tid & 3;       // B: 64 rows x 4 quarters, 2 cp16 each

    for (int t = blockIdx.x; t < total_tiles; t += gridDim.x) {
        int mtile = t >> 4;
        int jt    = t & 15;
        int jbase = jt * NT;

        __syncthreads();
        if (tid < MT) smeta[tid] = g_rows[mtile * MT + tid];
        sWf[tid] = Wf[jbase * 8 + tid];
        sWf[tid + 256] = Wf[jbase * 8 + tid + 256];

        const char* Ah_base = (const char*)(g_Ahi + (size_t)(mtile * MT + arow) * ENC) + ahalf * 64;
        const char* Al_base = (const char*)(g_Alo + (size_t)(mtile * MT + arow) * ENC) + ahalf * 64;
        const char* Bh_base = (const char*)(g_WvThi + (size_t)(jbase + brow) * ENC);
        const char* Bl_base = (const char*)(g_WvTlo + (size_t)(jbase + brow) * ENC);

        #define STAGE(kc_, buf_) do { \
            uint32_t sb_ = ab + (buf_) * ST_STRIDE; \
            _Pragma("unroll") \
            for (int q = 0; q < 4; q++) { \
                uint32_t o_ = SW128((uint32_t)(arow * 128 + ahalf * 64 + q * 16)); \
                cp16(sb_ + OFF_AH + o_, Ah_base + (kc_) * 128 + q * 16); \
                cp16(sb_ + OFF_AL + o_, Al_base + (kc_) * 128 + q * 16); \
            } \
            { \
                uint32_t o0_ = SW128((uint32_t)(brow * 128 + bq2 * 16)); \
                uint32_t o1_ = SW128((uint32_t)(brow * 128 + (bq2 + 4) * 16)); \
                cp16(sb_ + OFF_BH + o0_, Bh_base + (kc_) * 128 + bq2 * 16); \
                cp16(sb_ + OFF_BH + o1_, Bh_base + (kc_) * 128 + (bq2 + 4) * 16); \
                cp16(sb_ + OFF_BL + o0_, Bl_base + (kc_) * 128 + bq2 * 16); \
                cp16(sb_ + OFF_BL + o1_, Bl_base + (kc_) * 128 + (bq2 + 4) * 16); \
            } \
        } while (0)

        STAGE(0, 0);
        CP_COMMIT();

        float acc[8][4];
        #pragma unroll
        for (int nf = 0; nf < 8; nf++)
            #pragma unroll
            for (int q = 0; q < 4; q++) acc[nf][q] = 0.f;

        #pragma unroll
        for (int kc = 0; kc < ENC / KC; kc++) {
            __syncthreads();
            if (kc < ENC / KC - 1) {
                STAGE(kc + 1, (kc + 1) & 1);
                CP_COMMIT();
                CP_WAIT(1);
            } else {
                CP_WAIT(0);
            }
            __syncthreads();

            uint32_t mb = ab + (kc & 1) * ST_STRIDE;
            #pragma unroll
            for (int ks = 0; ks < 4; ks++) {
                uint32_t ah[4], al[4];
                ldsm4(ah, mb + OFF_AH + ((a_rb + ks * 32) ^ a_msk));
                ldsm4(al, mb + OFF_AL + ((a_rb + ks * 32) ^ a_msk));
                uint32_t bh[4][4], bl[4][4];
                #pragma unroll
                for (int p = 0; p < 4; p++) {
                    ldsm4(bh[p], mb + OFF_BH + ((b_rb[p] + ks * 32) ^ b_msk[p]));
                    ldsm4(bl[p], mb + OFF_BL + ((b_rb[p] + ks * 32) ^ b_msk[p]));
                }
                #pragma unroll
                for (int p = 0; p < 4; p++) {
                    mma16816(acc[p * 2],     ah, bh[p][0], bh[p][1]);
                    mma16816(acc[p * 2 + 1], ah, bh[p][2], bh[p][3]);
                }
                #pragma unroll
                for (int p = 0; p < 4; p++) {
                    mma16816(acc[p * 2],     ah, bl[p][0], bl[p][1]);
                    mma16816(acc[p * 2 + 1], ah, bl[p][2], bl[p][3]);
                }
                #pragma unroll
                for (int p = 0; p < 4; p++) {
                    mma16816(acc[p * 2],     al, bh[p][0], bh[p][1]);
                    mma16816(acc[p * 2 + 1], al, bh[p][2], bh[p][3]);
                }
            }
        }
        #undef STAGE

        // ---- epilogue: each warp owns rows wm..wm+15, full 64 j ----
        int r0 = wm + (lane >> 2);
        int r1 = r0 + 8;
        unsigned m0 = smeta[r0], m1 = smeta[r1];
        const float* qv0 = &g_qv[(m0 != SENT) ? (m0 >> 16) : 0][jbase];
        const float* qv1 = &g_qv[(m1 != SENT) ? (m1 >> 16) : 0][jbase];
        float pf0[8], pf1[8];
        #pragma unroll
        for (int h = 0; h < 8; h++) { pf0[h] = 0.f; pf1[h] = 0.f; }
        #pragma unroll
        for (int nf = 0; nf < 8; nf++) {
            int jl = nf * 8 + 2 * (lane & 3);
            float hv00 = (m0 != SENT) ? tanhf(qv0[jl]     + acc[nf][0]) : 0.f;
            float hv01 = (m0 != SENT) ? tanhf(qv0[jl + 1] + acc[nf][1]) : 0.f;
            float hv10 = (m1 != SENT) ? tanhf(qv1[jl]     + acc[nf][2]) : 0.f;
            float hv11 = (m1 != SENT) ? tanhf(qv1[jl + 1] + acc[nf][3]) : 0.f;
            const float* w0 = &sWf[jl * 8];
            const float* w1 = &sWf[(jl + 1) * 8];
            #pragma unroll
            for (int h = 0; h < 8; h++) {
                pf0[h] += hv00 * w0[h] + hv01 * w1[h];
                pf1[h] += hv10 * w0[h] + hv11 * w1[h];
            }
        }
        #pragma unroll
        for (int h = 0; h < 8; h++) {
            pf0[h] += __shfl_xor_sync(0xffffffffu, pf0[h], 1);
            pf0[h] += __shfl_xor_sync(0xffffffffu, pf0[h], 2);
            pf1[h] += __shfl_xor_sync(0xffffffffu, pf1[h], 1);
            pf1[h] += __shfl_xor_sync(0xffffffffu, pf1[h], 2);
        }
        if ((lane & 3) == 0) {
            if (m0 != SENT) {
                float* dst = &g_pf[m0 >> 16][m0 & 0xFFFF][jt * 8];
                *(float4*)dst       = make_float4(pf0[0], pf0[1], pf0[2], pf0[3]);
                *(float4*)(dst + 4) = make_float4(pf0[4], pf0[5], pf0[6], pf0[7]);
            }
            if (m1 != SENT) {
                float* dst = &g_pf[m1 >> 16][m1 & 0xFFFF][jt * 8];
                *(float4*)dst       = make_float4(pf1[0], pf1[1], pf1[2], pf1[3]);
                *(float4*)(dst + 4) = make_float4(pf1[4], pf1[5], pf1[6], pf1[7]);
            }
        }
    }
}

// ---------------- K2bc: partials -> score -> context ----------------
__global__ void __launch_bounds__(256) k2bc_score_ctx(const float* __restrict__ enc,
                                                      const float* __restrict__ bf,
                                                      const float* __restrict__ mask,
                                                      float* __restrict__ out_score) {
    int b  = blockIdx.x;
    int et = blockIdx.y;
    int lo = g_lo[b], hi = g_hi[b];
    int tx = threadIdx.x & 31;
    int h  = threadIdx.x >> 5;
    int eg = et * 32 + tx;

    __shared__ float sc[256][8];
    float a0 = 0.f, a1 = 0.f, a2 = 0.f, a3 = 0.f;
    float a4 = 0.f, a5 = 0.f, a6 = 0.f, a7 = 0.f;

    for (int st = lo; st <= hi; st += 256) {
        int tlen = hi - st + 1; if (tlen > 256) tlen = 256;
        __syncthreads();
        for (int idx = threadIdx.x; idx < tlen * 8; idx += 256) {
            int sr = idx >> 3, hh = idx & 7;
            int s = st + sr;
            const float* p = g_pf[b][s];
            float f = bf[hh];
            #pragma unroll
            for (int pp = 0; pp < 16; pp++) f += p[pp * 8 + hh];
            float alpha = softplusf(f) * mask[b * SEQ + s];
            float d = g_kap[b][hh] - (float)s;
            float scv = alpha * expf(-g_beta[b][hh] * d * d);
            sc[sr][hh] = scv;
            if (et == 0)
                out_score[((size_t)b * SEQ + s) * HEADS + hh] = scv;
        }
        __syncthreads();
        const float* ep = enc + ((size_t)b * SEQ + st) * ENC + eg;
        int sr = 0;
        for (; sr + 8 <= tlen; sr += 8) {
            a0 += sc[sr + 0][h] * ep[(size_t)(sr + 0) * ENC];
            a1 += sc[sr + 1][h] * ep[(size_t)(sr + 1) * ENC];
            a2 += sc[sr + 2][h] * ep[(size_t)(sr + 2) * ENC];
            a3 += sc[sr + 3][h] * ep[(size_t)(sr + 3) * ENC];
            a4 += sc[sr + 4][h] * ep[(size_t)(sr + 4) * ENC];
            a5 += sc[sr + 5][h] * ep[(size_t)(sr + 5) * ENC];
            a6 += sc[sr + 6][h] * ep[(size_t)(sr + 6) * ENC];
            a7 += sc[sr + 7][h] * ep[(size_t)(sr + 7) * ENC];
        }
        for (; sr < tlen; sr++)
            a0 += sc[sr][h] * ep[(size_t)sr * ENC];
    }
    g_ctx[b][h * ENC + eg] = ((a0 + a1) + (a2 + a3)) + ((a4 + a5) + (a6 + a7));
}

// ---------------- K4: context @ Wfc + bfc ----------------
__global__ void __launch_bounds__(256) k4_final(const float* __restrict__ Wfc,
                                                const float* __restrict__ bfc,
                                                float* __restrict__ out_ctx) {
    int et = blockIdx.x, bg = blockIdx.y;
    int tx = threadIdx.x & 31;
    int js = threadIdx.x >> 5;
    int e  = et * 32 + tx;
    int j0 = js * 512;

    __shared__ float sctx[8][8][65];

    float acc[8];
    #pragma unroll
    for (int b = 0; b < 8; b++) acc[b] = 0.f;

    for (int jc = 0; jc < 512; jc += 64) {
        __syncwarp();
        #pragma unroll
        for (int b = 0; b < 8; b++) {
            sctx[js][b][tx]      = g_ctx[bg * 8 + b][j0 + jc + tx];
            sctx[js][b][32 + tx] = g_ctx[bg * 8 + b][j0 + jc + 32 + tx];
        }
        __syncwarp();
        #pragma unroll 4
        for (int jj = 0; jj < 64; jj++) {
            float w = Wfc[(size_t)(j0 + jc + jj) * ENC + e];
            #pragma unroll
            for (int b = 0; b < 8; b++)
                acc[b] += sctx[js][b][jj] * w;
        }
    }

    __syncthreads();
    float* red = &sctx[0][0][0];
    #pragma unroll
    for (int b = 0; b < 8; b++) red[(js * 8 + b) * 32 + tx] = acc[b];
    __syncthreads();
    int ob = threadIdx.x >> 5;
    float s = 0.f;
    #pragma unroll
    for (int jj = 0; jj < 8; jj++) s += red[(jj * 8 + ob) * 32 + tx];
    out_ctx[(bg * 8 + ob) * ENC + e] = s + bfc[e];
}

// ---------------- launch ----------------
extern "C" void kernel_launch(void* const* d_in, const int* in_sizes, int n_in,
                              void* d_out, int out_size) {
    const float* enc   = (const float*)d_in[0];
    const float* dec   = (const float*)d_in[1];
    const float* kappa = (const float*)d_in[2];
    const float* mask  = (const float*)d_in[3];
    const float* Wv    = (const float*)d_in[4];
    const float* bv    = (const float*)d_in[5];
    const float* Wq    = (const float*)d_in[6];
    const float* bq    = (const float*)d_in[7];
    const float* Wf    = (const float*)d_in[8];
    const float* bf    = (const float*)d_in[9];
    const float* Wb    = (const float*)d_in[10];
    const float* bb    = (const float*)d_in[11];
    const float* Wk    = (const float*)d_in[12];
    const float* bk    = (const float*)d_in[13];
    const float* Wfc   = (const float*)d_in[14];
    const float* bfc   = (const float*)d_in[15];

    float* out_ctx   = (float*)d_out;
    float* out_kappa = out_ctx + BS * ENC;
    float* out_score = out_kappa + BS * HEADS;

    cudaFuncSetAttribute(k2a_mma, cudaFuncAttributeMaxDynamicSharedMemorySize, SMEM_DYN);

    k_nop<<<1, 32>>>();
    k_prep<<<800, 256>>>(Wv, dec, Wq, bq, bv, kappa, Wb, bb, Wk, bk, out_kappa);
    kE_split<<<dim3(64, 9), 256>>>(enc, out_score);
    k2a_mma<<<128, 256, SMEM_DYN>>>(Wf);
    k2bc_score_ctx<<<dim3(BS, 16), 256>>>(enc, bf, mask, out_score);
    k4_final<<<dim3(16, 4), 256>>>(Wfc, bfc, out_ctx);
}

// round 17
// speedup vs baseline: 1.0370x; 1.0370x over previous
#include <cuda_runtime.h>
#include <cuda_bf16.h>
#include <math.h>
#include <stdint.h>

#define BS    32
#define SEQ   2048
#define ENC   512
#define HEADS 8
#define IH    1024
#define DECIN 1024
#define SENT  0xFFFFFFFFu

#define MT 128
#define NT 64
#define NJT (IH / NT)
#define KC 64
#define MAXTILES 512

// ---------------- scratch ----------------
__device__ float         g_qv[BS][IH];
__device__ float         g_beta[BS][HEADS];
__device__ float         g_kap[BS][HEADS];
__device__ int           g_lo[BS];
__device__ int           g_hi[BS];
__device__ unsigned      g_rows[BS * SEQ + 128];
__device__ float         g_pf[BS][SEQ][NJT * HEADS];
__device__ float         g_ctx[BS][HEADS * ENC];
__device__ __nv_bfloat16 g_WvThi[IH * ENC];
__device__ __nv_bfloat16 g_WvTlo[IH * ENC];
__device__ __nv_bfloat16 g_Ahi[(size_t)MAXTILES * 128 * ENC];
__device__ __nv_bfloat16 g_Alo[(size_t)MAXTILES * 128 * ENC];
__device__ int           g_flag1;   // k0 done (32 arrivals)
__device__ int           g_flag2;   // k2bc done (512 arrivals)

__device__ __forceinline__ float softplusf(float x) {
    return fmaxf(x, 0.f) + log1pf(expf(-fabsf(x)));
}

#define SW128(x) ((x) ^ (((x) >> 3) & 0x70))

__device__ __forceinline__ uint32_t smem_u32(const void* p) {
    uint32_t a;
    asm("{ .reg .u64 t; cvta.to.shared.u64 t, %1; cvt.u32.u64 %0, t; }" : "=r"(a) : "l"(p));
    return a;
}
__device__ __forceinline__ void ldsm4(uint32_t* r, uint32_t addr) {
    asm volatile("ldmatrix.sync.aligned.m8n8.x4.shared.b16 {%0,%1,%2,%3}, [%4];"
                 : "=r"(r[0]), "=r"(r[1]), "=r"(r[2]), "=r"(r[3]) : "r"(addr));
}
__device__ __forceinline__ void mma16816(float* c, const uint32_t* a,
                                         uint32_t b0, uint32_t b1) {
    asm volatile("mma.sync.aligned.m16n8k16.row.col.f32.bf16.bf16.f32 "
                 "{%0,%1,%2,%3}, {%4,%5,%6,%7}, {%8,%9}, {%0,%1,%2,%3};"
                 : "+f"(c[0]), "+f"(c[1]), "+f"(c[2]), "+f"(c[3])
                 : "r"(a[0]), "r"(a[1]), "r"(a[2]), "r"(a[3]), "r"(b0), "r"(b1));
}
__device__ __forceinline__ void cp16(uint32_t dst, const void* src) {
    asm volatile("cp.async.cg.shared.global [%0], [%1], 16;" :: "r"(dst), "l"(src));
}
#define CP_COMMIT() asm volatile("cp.async.commit_group;" ::: "memory")
#define CP_WAIT(n)  asm volatile("cp.async.wait_group %0;" :: "n"(n) : "memory")

__device__ __forceinline__ void gate_wait(int* flag, int target, int tid) {
    if (tid == 0) {
        while (*(volatile int*)flag != target) __nanosleep(64);
    }
    __syncthreads();
    __threadfence();
}
__device__ __forceinline__ void gate_arrive(int* flag, int tid) {
    __syncthreads();
    if (tid == 0) {
        __threadfence();
        atomicAdd(flag, 1);
    }
}

// ================= P1: kW (0..511) + k1 (512..767) + k0 (768..799)
//                      + zero-score (800..863) + kE (864..1375, gated on k0) =================
__global__ void __launch_bounds__(256) k_p1(const float* __restrict__ Wv,
                                            const float* __restrict__ dec,
                                            const float* __restrict__ Wq,
                                            const float* __restrict__ bq,
                                            const float* __restrict__ bv,
                                            const float* __restrict__ kappa_in,
                                            const float* __restrict__ Wb,
                                            const float* __restrict__ bb,
                                            const float* __restrict__ Wk,
                                            const float* __restrict__ bk,
                                            const float* __restrict__ enc,
                                            float* __restrict__ out_kappa,
                                            float* __restrict__ out_score) {
    __shared__ float smem[4 * DECIN + 1024];
    int bid = blockIdx.x;
    int tid = threadIdx.x;

    if (bid == 0 && tid == 0) g_flag2 = 0;    // reset for this replay's P3

    if (bid < 512) {
        // ===== kW_split =====
        float (*s)[33] = (float (*)[33])smem;
        int k0 = (bid & 15) * 32, j0 = (bid >> 4) * 32;
        int jl = tid & 31, kq = tid >> 5;
        #pragma unroll
        for (int i = 0; i < 4; i++)
            s[kq * 4 + i][jl] = Wv[(size_t)(k0 + kq * 4 + i) * IH + j0 + jl];
        __syncthreads();
        int jr = tid >> 3;
        int kg = (tid & 7) * 4;
        __nv_bfloat16 hi[4], lo[4];
        #pragma unroll
        for (int i = 0; i < 4; i++) {
            float x = s[kg + i][jr];
            hi[i] = __float2bfloat16(x);
            lo[i] = __float2bfloat16(x - __bfloat162float(hi[i]));
        }
        size_t dst = (size_t)(j0 + jr) * ENC + k0 + kg;
        *(uint2*)(g_WvThi + dst) = *(const uint2*)hi;
        *(uint2*)(g_WvTlo + dst) = *(const uint2*)lo;
    } else if (bid < 768) {
        // ===== k1_query =====
        int id = bid - 512;
        int jt = id & 31, bg = id >> 5;
        int c  = tid & 31;
        int ks = tid >> 5;
        int j  = jt * 32 + c;
        float (*sdec)[DECIN] = (float (*)[DECIN])smem;
        float (*pacc)[4][32] = (float (*)[4][32])(smem + 4 * DECIN);
        for (int i = tid; i < 4 * DECIN; i += 256) {
            int bb2 = i >> 10, k = i & (DECIN - 1);
            sdec[bb2][k] = dec[(bg * 4 + bb2) * DECIN + k];
        }
        __syncthreads();
        float a0 = 0.f, a1 = 0.f, a2 = 0.f, a3 = 0.f;
        int k0 = ks * 128;
        #pragma unroll 16
        for (int k = k0; k < k0 + 128; k++) {
            float w = Wq[(size_t)k * IH + j];
            a0 += sdec[0][k] * w; a1 += sdec[1][k] * w;
            a2 += sdec[2][k] * w; a3 += sdec[3][k] * w;
        }
        pacc[ks][0][c] = a0; pacc[ks][1][c] = a1;
        pacc[ks][2][c] = a2; pacc[ks][3][c] = a3;
        __syncthreads();
        if (tid < 128) {
            int bb2 = tid >> 5;
            float s2 = 0.f;
            #pragma unroll
            for (int kk = 0; kk < 8; kk++) s2 += pacc[kk][bb2][c];
            g_qv[bg * 4 + bb2][j] = s2 + bq[j] + bv[j];
        }
    } else if (bid < 800) {
        // ===== k0_heads =====
        int b = bid - 768;
        float* sdec = smem;
        float* sred = smem + DECIN;
        float* sbeta = sred + 64;
        float* skap  = sbeta + HEADS;
        for (int i = tid; i < DECIN; i += 256)
            sdec[i] = dec[b * DECIN + i];
        __syncthreads();
        int w = tid >> 5, lane = tid & 31;
        int mat = w >> 2, q = w & 3;
        const float* W = (mat == 0) ? Wb : Wk;
        int base = q * 2048;
        float acc = 0.f;
        #pragma unroll 16
        for (int it = 0; it < 64; it++) {
            int e = base + it * 32 + lane;
            acc += sdec[e >> 3] * W[e];
        }
        acc += __shfl_xor_sync(0xffffffffu, acc, 8);
        acc += __shfl_xor_sync(0xffffffffu, acc, 16);
        if (lane < 8) sred[(mat * 4 + q) * 8 + lane] = acc;
        __syncthreads();
        if (tid < 16) {
            int h = tid & 7, mt2 = tid >> 3;
            float dot = sred[(mt2 * 4 + 0) * 8 + h] + sred[(mt2 * 4 + 1) * 8 + h]
                      + sred[(mt2 * 4 + 2) * 8 + h] + sred[(mt2 * 4 + 3) * 8 + h];
            if (mt2 == 0) {
                float bv2 = softplusf(dot + bb[h]);
                sbeta[h] = bv2;
                g_beta[b][h] = bv2;
            } else {
                float kv = kappa_in[b * HEADS + h] + softplusf(dot + bk[h]);
                skap[h] = kv;
                g_kap[b][h] = kv;
                out_kappa[b * HEADS + h] = kv;
            }
        }
        __syncthreads();
        if (tid == 0) {
            float lof = 1e30f, hif = -1e30f;
            for (int h = 0; h < HEADS; h++) {
                float R = sqrtf(110.f / sbeta[h]);
                lof = fminf(lof, skap[h] - R);
                hif = fmaxf(hif, skap[h] + R);
            }
            int lo, hi;
            if (hif < 0.f || lof > (float)(SEQ - 1)) { lo = 0; hi = -1; }
            else {
                lo = (int)floorf(lof); if (lo < 0) lo = 0;
                hi = (int)ceilf(hif);  if (hi > SEQ - 1) hi = SEQ - 1;
            }
            g_lo[b] = lo; g_hi[b] = hi;
        }
        gate_arrive(&g_flag1, tid);
    } else if (bid < 864) {
        // ===== zero out_score =====
        int id = bid - 800;
        uint4 z = make_uint4(0, 0, 0, 0);
        #pragma unroll
        for (int i = 0; i < 8; i++)
            ((uint4*)out_score)[(id * 8 + i) * 256 + tid] = z;
    } else {
        // ===== kE_split (gated on k0 flag) =====
        int id = bid - 864;          // 0..511
        int tile0 = id & 63;
        int byq   = id >> 6;         // 0..7
        gate_wait(&g_flag1, 32, tid);

        int* soff = (int*)smem;
        if (tid < 32) {
            int w = g_hi[tid] - g_lo[tid] + 1;
            if (w < 0) w = 0;
            int x = w;
            #pragma unroll
            for (int off = 1; off < 32; off <<= 1) {
                int y = __shfl_up_sync(0xffffffffu, x, off);
                if (tid >= off) x += y;
            }
            soff[tid + 1] = x;
            if (tid == 0) soff[0] = 0;
        }
        __syncthreads();
        int total = soff[BS];
        int snt = (total + 127) / 128;
        if (snt < 1) snt = 1;

        int row  = tid >> 1;
        int half = tid & 1;
        int colb = byq * 64 + half * 32;

        for (int tile = tile0; tile < snt; tile += 64) {
            int grow = tile * 128 + row;
            unsigned m = SENT;
            if (grow < total) {
                int b = 0;
                #pragma unroll 8
                while (b < BS - 1 && grow >= soff[b + 1]) b++;
                m = ((unsigned)b << 16) | (unsigned)(g_lo[b] + (grow - soff[b]));
            }
            if (byq == 0 && half == 0)
                g_rows[grow] = m;

            size_t dbase = (size_t)grow * ENC + colb;
            if (m == SENT) {
                uint4 z = make_uint4(0, 0, 0, 0);
                #pragma unroll
                for (int q = 0; q < 4; q++) {
                    ((uint4*)(g_Ahi + dbase))[q] = z;
                    ((uint4*)(g_Alo + dbase))[q] = z;
                }
                continue;
            }
            const float4* src = (const float4*)(enc + ((size_t)(m >> 16) * SEQ + (m & 0xFFFF)) * ENC + colb);
            #pragma unroll
            for (int q = 0; q < 4; q++) {
                float4 v0 = src[q * 2], v1 = src[q * 2 + 1];
                float x[8] = {v0.x, v0.y, v0.z, v0.w, v1.x, v1.y, v1.z, v1.w};
                __nv_bfloat16 hi[8], lo[8];
                #pragma unroll
                for (int i = 0; i < 8; i++) {
                    hi[i] = __float2bfloat16(x[i]);
                    lo[i] = __float2bfloat16(x[i] - __bfloat162float(hi[i]));
                }
                ((uint4*)(g_Ahi + dbase))[q] = *(const uint4*)hi;
                ((uint4*)(g_Alo + dbase))[q] = *(const uint4*)lo;
            }
        }
    }
}

// ================= P2: k2a (128x64 tiles, 8 warps, cp.async pipeline) =================
#define ST_STRIDE 49152
#define OFF_AH 0
#define OFF_AL 16384
#define OFF_BH 32768
#define OFF_BL 40960
#define OFF_WF   (2 * ST_STRIDE)
#define OFF_META (OFF_WF + 2048)
#define SMEM_DYN (OFF_META + 512 + 1024)

__global__ void __launch_bounds__(256) k2a_mma(const float* __restrict__ Wf) {
    extern __shared__ char dsm[];
    uint32_t b0 = smem_u32(dsm);
    uint32_t ab = (b0 + 1023u) & ~1023u;
    char* dyn = dsm + (ab - b0);
    float*    sWf   = (float*)(dyn + OFF_WF);
    unsigned* smeta = (unsigned*)(dyn + OFF_META);
    __shared__ int s_tt;

    int tid  = threadIdx.x;
    int wid  = tid >> 5, lane = tid & 31;

    if (blockIdx.x == 0 && tid == 0) g_flag1 = 0;   // reset for next replay's P1

    if (tid == 0) {
        int off = 0;
        for (int b = 0; b < BS; b++) {
            int w = g_hi[b] - g_lo[b] + 1;
            if (w > 0) off += w;
        }
        int n128 = (off + MT - 1) / MT;
        if (n128 < 1) n128 = 1;
        s_tt = n128 * NJT;
    }
    __syncthreads();
    int total_tiles = s_tt;

    int wm = wid * 16;
    uint32_t a_rb  = (uint32_t)((wm + (lane & 15)) * 128 + ((lane & 16) ? 16 : 0));
    uint32_t a_msk = (a_rb >> 3) & 0x70;
    uint32_t b_rb[4], b_msk[4];
    #pragma unroll
    for (int p = 0; p < 4; p++) {
        int n = p * 16 + (lane & 7) + ((lane & 16) ? 8 : 0);
        b_rb[p]  = (uint32_t)(n * 128 + ((lane & 8) ? 16 : 0));
        b_msk[p] = (b_rb[p] >> 3) & 0x70;
    }

    int arow = tid >> 1, ahalf = tid & 1;
    int brow = tid >> 2, bq2 = tid & 3;

    for (int t = blockIdx.x; t < total_tiles; t += gridDim.x) {
        int mtile = t >> 4;
        int jt    = t & 15;
        int jbase = jt * NT;

        __syncthreads();
        if (tid < MT) smeta[tid] = g_rows[mtile * MT + tid];
        sWf[tid] = Wf[jbase * 8 + tid];
        sWf[tid + 256] = Wf[jbase * 8 + tid + 256];

        const char* Ah_base = (const char*)(g_Ahi + (size_t)(mtile * MT + arow) * ENC) + ahalf * 64;
        const char* Al_base = (const char*)(g_Alo + (size_t)(mtile * MT + arow) * ENC) + ahalf * 64;
        const char* Bh_base = (const char*)(g_WvThi + (size_t)(jbase + brow) * ENC);
        const char* Bl_base = (const char*)(g_WvTlo + (size_t)(jbase + brow) * ENC);

        #define STAGE(kc_, buf_) do { \
            uint32_t sb_ = ab + (buf_) * ST_STRIDE; \
            _Pragma("unroll") \
            for (int q = 0; q < 4; q++) { \
                uint32_t o_ = SW128((uint32_t)(arow * 128 + ahalf * 64 + q * 16)); \
                cp16(sb_ + OFF_AH + o_, Ah_base + (kc_) * 128 + q * 16); \
                cp16(sb_ + OFF_AL + o_, Al_base + (kc_) * 128 + q * 16); \
            } \
            { \
                uint32_t o0_ = SW128((uint32_t)(brow * 128 + bq2 * 16)); \
                uint32_t o1_ = SW128((uint32_t)(brow * 128 + (bq2 + 4) * 16)); \
                cp16(sb_ + OFF_BH + o0_, Bh_base + (kc_) * 128 + bq2 * 16); \
                cp16(sb_ + OFF_BH + o1_, Bh_base + (kc_) * 128 + (bq2 + 4) * 16); \
                cp16(sb_ + OFF_BL + o0_, Bl_base + (kc_) * 128 + bq2 * 16); \
                cp16(sb_ + OFF_BL + o1_, Bl_base + (kc_) * 128 + (bq2 + 4) * 16); \
            } \
        } while (0)

        STAGE(0, 0);
        CP_COMMIT();

        float acc[8][4];
        #pragma unroll
        for (int nf = 0; nf < 8; nf++)
            #pragma unroll
            for (int q = 0; q < 4; q++) acc[nf][q] = 0.f;

        #pragma unroll
        for (int kc = 0; kc < ENC / KC; kc++) {
            __syncthreads();
            if (kc < ENC / KC - 1) {
                STAGE(kc + 1, (kc + 1) & 1);
                CP_COMMIT();
                CP_WAIT(1);
            } else {
                CP_WAIT(0);
            }
            __syncthreads();

            uint32_t mb = ab + (kc & 1) * ST_STRIDE;
            #pragma unroll
            for (int ks = 0; ks < 4; ks++) {
                uint32_t ah[4], al[4];
                ldsm4(ah, mb + OFF_AH + ((a_rb + ks * 32) ^ a_msk));
                ldsm4(al, mb + OFF_AL + ((a_rb + ks * 32) ^ a_msk));
                uint32_t bh[4][4], bl[4][4];
                #pragma unroll
                for (int p = 0; p < 4; p++) {
                    ldsm4(bh[p], mb + OFF_BH + ((b_rb[p] + ks * 32) ^ b_msk[p]));
                    ldsm4(bl[p], mb + OFF_BL + ((b_rb[p] + ks * 32) ^ b_msk[p]));
                }
                #pragma unroll
                for (int p = 0; p < 4; p++) {
                    mma16816(acc[p * 2],     ah, bh[p][0], bh[p][1]);
                    mma16816(acc[p * 2 + 1], ah, bh[p][2], bh[p][3]);
                }
                #pragma unroll
                for (int p = 0; p < 4; p++) {
                    mma16816(acc[p * 2],     ah, bl[p][0], bl[p][1]);
                    mma16816(acc[p * 2 + 1], ah, bl[p][2], bl[p][3]);
                }
                #pragma unroll
                for (int p = 0; p < 4; p++) {
                    mma16816(acc[p * 2],     al, bh[p][0], bh[p][1]);
                    mma16816(acc[p * 2 + 1], al, bh[p][2], bh[p][3]);
                }
            }
        }
        #undef STAGE

        int r0 = wm + (lane >> 2);
        int r1 = r0 + 8;
        unsigned m0 = smeta[r0], m1 = smeta[r1];
        const float* qv0 = &g_qv[(m0 != SENT) ? (m0 >> 16) : 0][jbase];
        const float* qv1 = &g_qv[(m1 != SENT) ? (m1 >> 16) : 0][jbase];
        float pf0[8], pf1[8];
        #pragma unroll
        for (int h = 0; h < 8; h++) { pf0[h] = 0.f; pf1[h] = 0.f; }
        #pragma unroll
        for (int nf = 0; nf < 8; nf++) {
            int jl = nf * 8 + 2 * (lane & 3);
            float hv00 = (m0 != SENT) ? tanhf(qv0[jl]     + acc[nf][0]) : 0.f;
            float hv01 = (m0 != SENT) ? tanhf(qv0[jl + 1] + acc[nf][1]) : 0.f;
            float hv10 = (m1 != SENT) ? tanhf(qv1[jl]     + acc[nf][2]) : 0.f;
            float hv11 = (m1 != SENT) ? tanhf(qv1[jl + 1] + acc[nf][3]) : 0.f;
            const float* w0 = &sWf[jl * 8];
            const float* w1 = &sWf[(jl + 1) * 8];
            #pragma unroll
            for (int h = 0; h < 8; h++) {
                pf0[h] += hv00 * w0[h] + hv01 * w1[h];
                pf1[h] += hv10 * w0[h] + hv11 * w1[h];
            }
        }
        #pragma unroll
        for (int h = 0; h < 8; h++) {
            pf0[h] += __shfl_xor_sync(0xffffffffu, pf0[h], 1);
            pf0[h] += __shfl_xor_sync(0xffffffffu, pf0[h], 2);
            pf1[h] += __shfl_xor_sync(0xffffffffu, pf1[h], 1);
            pf1[h] += __shfl_xor_sync(0xffffffffu, pf1[h], 2);
        }
        if ((lane & 3) == 0) {
            if (m0 != SENT) {
                float* dst = &g_pf[m0 >> 16][m0 & 0xFFFF][jt * 8];
                *(float4*)dst       = make_float4(pf0[0], pf0[1], pf0[2], pf0[3]);
                *(float4*)(dst + 4) = make_float4(pf0[4], pf0[5], pf0[6], pf0[7]);
            }
            if (m1 != SENT) {
                float* dst = &g_pf[m1 >> 16][m1 & 0xFFFF][jt * 8];
                *(float4*)dst       = make_float4(pf1[0], pf1[1], pf1[2], pf1[3]);
                *(float4*)(dst + 4) = make_float4(pf1[4], pf1[5], pf1[6], pf1[7]);
            }
        }
    }
}

// ================= P3: k2bc (0..511) + k4 (512..575, gated) =================
__global__ void __launch_bounds__(256) k_p3(const float* __restrict__ enc,
                                            const float* __restrict__ bf,
                                            const float* __restrict__ mask,
                                            const float* __restrict__ Wfc,
                                            const float* __restrict__ bfc,
                                            float* __restrict__ out_score,
                                            float* __restrict__ out_ctx) {
    __shared__ float smem[8 * 8 * 65];
    int bid = blockIdx.x;
    int tid = threadIdx.x;

    if (bid < 512) {
        // ===== k2bc =====
        int b  = bid & 31;
        int et = bid >> 5;
        int lo = g_lo[b], hi = g_hi[b];
        int tx = tid & 31;
        int h  = tid >> 5;
        int eg = et * 32 + tx;

        float (*sc)[8] = (float (*)[8])smem;
        float a0 = 0.f, a1 = 0.f, a2 = 0.f, a3 = 0.f;
        float a4 = 0.f, a5 = 0.f, a6 = 0.f, a7 = 0.f;

        for (int st = lo; st <= hi; st += 256) {
            int tlen = hi - st + 1; if (tlen > 256) tlen = 256;
            __syncthreads();
            for (int idx = tid; idx < tlen * 8; idx += 256) {
                int sr = idx >> 3, hh = idx & 7;
                int s = st + sr;
                const float* p = g_pf[b][s];
                float f = bf[hh];
                #pragma unroll
                for (int pp = 0; pp < 16; pp++) f += p[pp * 8 + hh];
                float alpha = softplusf(f) * mask[b * SEQ + s];
                float d = g_kap[b][hh] - (float)s;
                float scv = alpha * expf(-g_beta[b][hh] * d * d);
                sc[sr][hh] = scv;
                if (et == 0)
                    out_score[((size_t)b * SEQ + s) * HEADS + hh] = scv;
            }
            __syncthreads();
            const float* ep = enc + ((size_t)b * SEQ + st) * ENC + eg;
            int sr = 0;
            for (; sr + 8 <= tlen; sr += 8) {
                a0 += sc[sr + 0][h] * ep[(size_t)(sr + 0) * ENC];
                a1 += sc[sr + 1][h] * ep[(size_t)(sr + 1) * ENC];
                a2 += sc[sr + 2][h] * ep[(size_t)(sr + 2) * ENC];
                a3 += sc[sr + 3][h] * ep[(size_t)(sr + 3) * ENC];
                a4 += sc[sr + 4][h] * ep[(size_t)(sr + 4) * ENC];
                a5 += sc[sr + 5][h] * ep[(size_t)(sr + 5) * ENC];
                a6 += sc[sr + 6][h] * ep[(size_t)(sr + 6) * ENC];
                a7 += sc[sr + 7][h] * ep[(size_t)(sr + 7) * ENC];
            }
            for (; sr < tlen; sr++)
                a0 += sc[sr][h] * ep[(size_t)sr * ENC];
        }
        g_ctx[b][h * ENC + eg] = ((a0 + a1) + (a2 + a3)) + ((a4 + a5) + (a6 + a7));
        gate_arrive(&g_flag2, tid);
    } else {
        // ===== k4 (gated on all k2bc blocks) =====
        gate_wait(&g_flag2, 512, tid);
        int id = bid - 512;
        int et = id & 15, bg = id >> 4;
        int tx = tid & 31;
        int js = tid >> 5;
        int e  = et * 32 + tx;
        int j0 = js * 512;

        float (*sctx)[8][65] = (float (*)[8][65])smem;

        float acc[8];
        #pragma unroll
        for (int b = 0; b < 8; b++) acc[b] = 0.f;

        for (int jc = 0; jc < 512; jc += 64) {
            __syncwarp();
            #pragma unroll
            for (int b = 0; b < 8; b++) {
                sctx[js][b][tx]      = g_ctx[bg * 8 + b][j0 + jc + tx];
                sctx[js][b][32 + tx] = g_ctx[bg * 8 + b][j0 + jc + 32 + tx];
            }
            __syncwarp();
            #pragma unroll 4
            for (int jj = 0; jj < 64; jj++) {
                float w = Wfc[(size_t)(j0 + jc + jj) * ENC + e];
                #pragma unroll
                for (int b = 0; b < 8; b++)
                    acc[b] += sctx[js][b][jj] * w;
            }
        }

        __syncthreads();
        float* red = smem;
        #pragma unroll
        for (int b = 0; b < 8; b++) red[(js * 8 + b) * 32 + tx] = acc[b];
        __syncthreads();
        int ob = tid >> 5;
        float s = 0.f;
        #pragma unroll
        for (int jj = 0; jj < 8; jj++) s += red[(jj * 8 + ob) * 32 + tx];
        out_ctx[(bg * 8 + ob) * ENC + e] = s + bfc[e];
    }
}

// ---------------- launch ----------------
extern "C" void kernel_launch(void* const* d_in, const int* in_sizes, int n_in,
                              void* d_out, int out_size) {
    const float* enc   = (const float*)d_in[0];
    const float* dec   = (const float*)d_in[1];
    const float* kappa = (const float*)d_in[2];
    const float* mask  = (const float*)d_in[3];
    const float* Wv    = (const float*)d_in[4];
    const float* bv    = (const float*)d_in[5];
    const float* Wq    = (const float*)d_in[6];
    const float* bq    = (const float*)d_in[7];
    const float* Wf    = (const float*)d_in[8];
    const float* bf    = (const float*)d_in[9];
    const float* Wb    = (const float*)d_in[10];
    const float* bb    = (const float*)d_in[11];
    const float* Wk    = (const float*)d_in[12];
    const float* bk    = (const float*)d_in[13];
    const float* Wfc   = (const float*)d_in[14];
    const float* bfc   = (const float*)d_in[15];

    float* out_ctx   = (float*)d_out;
    float* out_kappa = out_ctx + BS * ENC;
    float* out_score = out_kappa + BS * HEADS;

    cudaFuncSetAttribute(k2a_mma, cudaFuncAttributeMaxDynamicSharedMemorySize, SMEM_DYN);

    k_p1<<<1376, 256>>>(Wv, dec, Wq, bq, bv, kappa, Wb, bb, Wk, bk, enc,
                        out_kappa, out_score);
    k2a_mma<<<128, 256, SMEM_DYN>>>(Wf);
    k_p3<<<576, 256>>>(enc, bf, mask, Wfc, bfc, out_score, out_ctx);
}